// round 8
// baseline (speedup 1.0000x reference)
#include <cuda_runtime.h>

// BoundaryAwareBCELoss — fused 3x3 binary morphology boundary + weighted BCE mean.
// R8: occupancy push — __launch_bounds__(256,6) (48 warps/SM, was 40),
// unroll 2 + rolling row pointers + |s-4.5|<4 boundary test to fit 42 regs.
// Contiguous per-image row partitions (32 images × 23 blocks = 736, all
// resident), binary window-sum boundary, shuffle horizontal combine, fused
// threadfence final reduction (single launch).

#define IMG_W  1024
#define IMG_H  1024
#define IMG_B  32
#define BPI    23                        // blocks per image
#define GRID   (IMG_B * BPI)             // 736
#define NPIXD  ((double)IMG_B * IMG_H * IMG_W)

__device__ float g_partial[GRID];
__device__ unsigned int g_count;         // zero at load; reset by last block

__global__ __launch_bounds__(256, 6) void babce_kernel(
    const float* __restrict__ pred, const float* __restrict__ target,
    float* __restrict__ out)
{
    __shared__ float s_warp[8];
    __shared__ bool  s_last;

    const int tid  = threadIdx.x;
    const int lane = tid & 31;
    const int wid  = tid >> 5;

    const int b     = blockIdx.x / BPI;      // image
    const int chunk = blockIdx.x % BPI;      // row-range within image
    const int ys    = (chunk * IMG_H) / BPI;
    const int ye    = ((chunk + 1) * IMG_H) / BPI;   // 44 or 45 rows

    const int c0 = wid * 128;                 // warp column base
    const int x0 = c0 + lane * 4;             // this thread's 4 columns
    const bool is_edge = (lane == 0) || (lane == 31);
    // clamped halo column: duplication preserves window value-support,
    // so the binary-sum boundary test stays exact at image borders
    const int hcol = (lane == 0) ? ((c0 > 0) ? c0 - 1 : 0)
                                 : ((c0 + 128 < IMG_W) ? c0 + 128 : IMG_W - 1);

    const float* __restrict__ timg = target + (size_t)b * IMG_H * IMG_W;
    const float* __restrict__ pimg = pred   + (size_t)b * IMG_H * IMG_W;

    // rolling row pointers (advance by IMG_W per iteration)
    const int yu = (ys > 0) ? ys - 1 : 0;
    const float* trow = timg + (size_t)ys * IMG_W;   // row y (center)
    const float* prow = pimg + (size_t)ys * IMG_W;

    float4 tu = *(const float4*)(timg + (size_t)yu * IMG_W + x0);
    float4 tm = *(const float4*)(trow + x0);
    float hu = 0.f, hm = 0.f;
    if (is_edge) {
        hu = timg[(size_t)yu * IMG_W + hcol];
        hm = trow[hcol];
    }

    float sum = 0.0f;

    #pragma unroll 2
    for (int y = ys; y < ye; y++) {
        const int dd = (y < IMG_H - 1) ? IMG_W : 0;    // clamped next row
        const float4 td = *(const float4*)(trow + dd + x0);
        const float4 pp = *(const float4*)(prow + x0);
        float hd = 0.f;
        if (is_edge) hd = trow[dd + hcol];

        // vertical running sums (exact: values are 0.0 / 1.0)
        float4 vs;
        vs.x = tu.x + tm.x + td.x;
        vs.y = tu.y + tm.y + td.y;
        vs.z = tu.z + tm.z + td.z;
        vs.w = tu.w + tm.w + td.w;
        const float hvs = hu + hm + hd;

        // neighbor column sums across lanes
        float ls = __shfl_up_sync  (0xFFFFFFFFu, vs.w, 1);
        float rs = __shfl_down_sync(0xFFFFFFFFu, vs.x, 1);
        if (lane == 0)  ls = hvs;
        if (lane == 31) rs = hvs;

        // horizontal 3-tap sums; boundary <=> window sum in [1,8] <=> |s-4.5|<4
        const float s0 = ls   + vs.x + vs.y;
        const float s1 = vs.x + vs.y + vs.z;
        const float s2 = vs.y + vs.z + vs.w;
        const float s3 = vs.z + vs.w + rs;

        float arg, w;
        arg = (tm.x > 0.5f) ? pp.x : (1.0f - pp.x);
        w   = (fabsf(s0 - 4.5f) < 4.0f) ? 3.0f : 1.0f;
        sum = fmaf(w, -__logf(arg), sum);

        arg = (tm.y > 0.5f) ? pp.y : (1.0f - pp.y);
        w   = (fabsf(s1 - 4.5f) < 4.0f) ? 3.0f : 1.0f;
        sum = fmaf(w, -__logf(arg), sum);

        arg = (tm.z > 0.5f) ? pp.z : (1.0f - pp.z);
        w   = (fabsf(s2 - 4.5f) < 4.0f) ? 3.0f : 1.0f;
        sum = fmaf(w, -__logf(arg), sum);

        arg = (tm.w > 0.5f) ? pp.w : (1.0f - pp.w);
        w   = (fabsf(s3 - 4.5f) < 4.0f) ? 3.0f : 1.0f;
        sum = fmaf(w, -__logf(arg), sum);

        tu = tm;  tm = td;
        hu = hm;  hm = hd;
        trow += IMG_W;  prow += IMG_W;
    }

    // ---- one block reduction at exit (fp32) ----
    #pragma unroll
    for (int off = 16; off > 0; off >>= 1)
        sum += __shfl_xor_sync(0xFFFFFFFFu, sum, off);
    if (lane == 0) s_warp[wid] = sum;
    __syncthreads();

    if (tid == 0) {
        float v = 0.0f;
        #pragma unroll
        for (int i = 0; i < 8; i++) v += s_warp[i];
        g_partial[blockIdx.x] = v;
        __threadfence();
        const unsigned done = atomicAdd(&g_count, 1u);
        s_last = (done == GRID - 1);
    }
    __syncthreads();

    // ---- last block: final fp32 tree reduction over 736 partials ----
    if (s_last) {
        __threadfence();
        float v = g_partial[tid] + g_partial[tid + 256];
        if (tid < GRID - 512) v += g_partial[tid + 512];
        #pragma unroll
        for (int off = 16; off > 0; off >>= 1)
            v += __shfl_xor_sync(0xFFFFFFFFu, v, off);
        if (lane == 0) s_warp[wid] = v;
        __syncthreads();
        if (tid == 0) {
            float t = 0.0f;
            #pragma unroll
            for (int i = 0; i < 8; i++) t += s_warp[i];
            out[0] = (float)((double)t / NPIXD);
            g_count = 0;   // restore for next graph replay (deterministic)
        }
    }
}

extern "C" void kernel_launch(void* const* d_in, const int* in_sizes, int n_in,
                              void* d_out, int out_size)
{
    const float* pred   = (const float*)d_in[0];
    const float* target = (const float*)d_in[1];
    float* out = (float*)d_out;

    babce_kernel<<<GRID, 256>>>(pred, target, out);
}

// round 11
// speedup vs baseline: 1.0491x; 1.0491x over previous
#include <cuda_runtime.h>

// BoundaryAwareBCELoss — fused 3x3 binary morphology boundary + weighted BCE mean.
// R9: grid scaled to the 6-block/SM cap: 32 images × 27 blocks = 864 (≤ 888
// resident capacity, single wave, 124 SMs × 6 + 24 × 5). 40-reg body from R8
// (unroll 2, rolling row pointers, |s-4.5|<4 boundary test). Binary window-sum
// boundary, shuffle horizontal combine, fused threadfence final reduction.

#define IMG_W  1024
#define IMG_H  1024
#define IMG_B  32
#define BPI    27                        // blocks per image
#define GRID   (IMG_B * BPI)             // 864
#define NPIXD  ((double)IMG_B * IMG_H * IMG_W)

__device__ float g_partial[GRID];
__device__ unsigned int g_count;         // zero at load; reset by last block

__global__ __launch_bounds__(256, 6) void babce_kernel(
    const float* __restrict__ pred, const float* __restrict__ target,
    float* __restrict__ out)
{
    __shared__ float s_warp[8];
    __shared__ bool  s_last;

    const int tid  = threadIdx.x;
    const int lane = tid & 31;
    const int wid  = tid >> 5;

    const int b     = blockIdx.x / BPI;      // image
    const int chunk = blockIdx.x % BPI;      // row-range within image
    const int ys    = (chunk * IMG_H) / BPI;
    const int ye    = ((chunk + 1) * IMG_H) / BPI;   // 37 or 38 rows

    const int c0 = wid * 128;                 // warp column base
    const int x0 = c0 + lane * 4;             // this thread's 4 columns
    const bool is_edge = (lane == 0) || (lane == 31);
    // clamped halo column: duplication preserves window value-support,
    // so the binary-sum boundary test stays exact at image borders
    const int hcol = (lane == 0) ? ((c0 > 0) ? c0 - 1 : 0)
                                 : ((c0 + 128 < IMG_W) ? c0 + 128 : IMG_W - 1);

    const float* __restrict__ timg = target + (size_t)b * IMG_H * IMG_W;
    const float* __restrict__ pimg = pred   + (size_t)b * IMG_H * IMG_W;

    // rolling row pointers (advance by IMG_W per iteration)
    const int yu = (ys > 0) ? ys - 1 : 0;
    const float* trow = timg + (size_t)ys * IMG_W;   // row y (center)
    const float* prow = pimg + (size_t)ys * IMG_W;

    float4 tu = *(const float4*)(timg + (size_t)yu * IMG_W + x0);
    float4 tm = *(const float4*)(trow + x0);
    float hu = 0.f, hm = 0.f;
    if (is_edge) {
        hu = timg[(size_t)yu * IMG_W + hcol];
        hm = trow[hcol];
    }

    float sum = 0.0f;

    #pragma unroll 2
    for (int y = ys; y < ye; y++) {
        const int dd = (y < IMG_H - 1) ? IMG_W : 0;    // clamped next row
        const float4 td = *(const float4*)(trow + dd + x0);
        const float4 pp = *(const float4*)(prow + x0);
        float hd = 0.f;
        if (is_edge) hd = trow[dd + hcol];

        // vertical running sums (exact: values are 0.0 / 1.0)
        float4 vs;
        vs.x = tu.x + tm.x + td.x;
        vs.y = tu.y + tm.y + td.y;
        vs.z = tu.z + tm.z + td.z;
        vs.w = tu.w + tm.w + td.w;
        const float hvs = hu + hm + hd;

        // neighbor column sums across lanes
        float ls = __shfl_up_sync  (0xFFFFFFFFu, vs.w, 1);
        float rs = __shfl_down_sync(0xFFFFFFFFu, vs.x, 1);
        if (lane == 0)  ls = hvs;
        if (lane == 31) rs = hvs;

        // horizontal 3-tap sums; boundary <=> window sum in [1,8] <=> |s-4.5|<4
        const float s0 = ls   + vs.x + vs.y;
        const float s1 = vs.x + vs.y + vs.z;
        const float s2 = vs.y + vs.z + vs.w;
        const float s3 = vs.z + vs.w + rs;

        float arg, w;
        arg = (tm.x > 0.5f) ? pp.x : (1.0f - pp.x);
        w   = (fabsf(s0 - 4.5f) < 4.0f) ? 3.0f : 1.0f;
        sum = fmaf(w, -__logf(arg), sum);

        arg = (tm.y > 0.5f) ? pp.y : (1.0f - pp.y);
        w   = (fabsf(s1 - 4.5f) < 4.0f) ? 3.0f : 1.0f;
        sum = fmaf(w, -__logf(arg), sum);

        arg = (tm.z > 0.5f) ? pp.z : (1.0f - pp.z);
        w   = (fabsf(s2 - 4.5f) < 4.0f) ? 3.0f : 1.0f;
        sum = fmaf(w, -__logf(arg), sum);

        arg = (tm.w > 0.5f) ? pp.w : (1.0f - pp.w);
        w   = (fabsf(s3 - 4.5f) < 4.0f) ? 3.0f : 1.0f;
        sum = fmaf(w, -__logf(arg), sum);

        tu = tm;  tm = td;
        hu = hm;  hm = hd;
        trow += IMG_W;  prow += IMG_W;
    }

    // ---- one block reduction at exit (fp32) ----
    #pragma unroll
    for (int off = 16; off > 0; off >>= 1)
        sum += __shfl_xor_sync(0xFFFFFFFFu, sum, off);
    if (lane == 0) s_warp[wid] = sum;
    __syncthreads();

    if (tid == 0) {
        float v = 0.0f;
        #pragma unroll
        for (int i = 0; i < 8; i++) v += s_warp[i];
        g_partial[blockIdx.x] = v;
        __threadfence();
        const unsigned done = atomicAdd(&g_count, 1u);
        s_last = (done == GRID - 1);
    }
    __syncthreads();

    // ---- last block: final fp32 tree reduction over 864 partials ----
    if (s_last) {
        __threadfence();
        float v = g_partial[tid] + g_partial[tid + 256] + g_partial[tid + 512];
        if (tid < GRID - 768) v += g_partial[tid + 768];
        #pragma unroll
        for (int off = 16; off > 0; off >>= 1)
            v += __shfl_xor_sync(0xFFFFFFFFu, v, off);
        if (lane == 0) s_warp[wid] = v;
        __syncthreads();
        if (tid == 0) {
            float t = 0.0f;
            #pragma unroll
            for (int i = 0; i < 8; i++) t += s_warp[i];
            out[0] = (float)((double)t / NPIXD);
            g_count = 0;   // restore for next graph replay (deterministic)
        }
    }
}

extern "C" void kernel_launch(void* const* d_in, const int* in_sizes, int n_in,
                              void* d_out, int out_size)
{
    const float* pred   = (const float*)d_in[0];
    const float* target = (const float*)d_in[1];
    float* out = (float*)d_out;

    babce_kernel<<<GRID, 256>>>(pred, target, out);
}

// round 12
// speedup vs baseline: 1.0598x; 1.0102x over previous
#include <cuda_runtime.h>

// BoundaryAwareBCELoss — fused 3x3 binary morphology boundary + weighted BCE mean.
// R12: unroll-4 load batching (R7's best-ncu body) combined with the 6-block/SM
// single-wave grid (R9): 32 images × 27 blocks = 864, __launch_bounds__(256,6)
// forcing the 40-reg fit. Binary window-sum boundary (|s-4.5|<4), rolling row
// pointers, shuffle horizontal combine, fused threadfence final reduction.

#define IMG_W  1024
#define IMG_H  1024
#define IMG_B  32
#define BPI    27                        // blocks per image
#define GRID   (IMG_B * BPI)             // 864 <= 148*6 = 888 (single wave)
#define NPIXD  ((double)IMG_B * IMG_H * IMG_W)

__device__ float g_partial[GRID];
__device__ unsigned int g_count;         // zero at load; reset by last block

__global__ __launch_bounds__(256, 6) void babce_kernel(
    const float* __restrict__ pred, const float* __restrict__ target,
    float* __restrict__ out)
{
    __shared__ float s_warp[8];
    __shared__ bool  s_last;

    const int tid  = threadIdx.x;
    const int lane = tid & 31;
    const int wid  = tid >> 5;

    const int b     = blockIdx.x / BPI;      // image
    const int chunk = blockIdx.x % BPI;      // row-range within image
    const int ys    = (chunk * IMG_H) / BPI;
    const int ye    = ((chunk + 1) * IMG_H) / BPI;   // 37 or 38 rows

    const int c0 = wid * 128;                 // warp column base
    const int x0 = c0 + lane * 4;             // this thread's 4 columns
    const bool is_edge = (lane == 0) || (lane == 31);
    // clamped halo column: duplication preserves window value-support,
    // so the binary-sum boundary test stays exact at image borders
    const int hcol = (lane == 0) ? ((c0 > 0) ? c0 - 1 : 0)
                                 : ((c0 + 128 < IMG_W) ? c0 + 128 : IMG_W - 1);

    const float* __restrict__ timg = target + (size_t)b * IMG_H * IMG_W;
    const float* __restrict__ pimg = pred   + (size_t)b * IMG_H * IMG_W;

    // rolling row pointers (advance by IMG_W per iteration)
    const int yu = (ys > 0) ? ys - 1 : 0;
    const float* trow = timg + (size_t)ys * IMG_W;   // row y (center)
    const float* prow = pimg + (size_t)ys * IMG_W;

    float4 tu = *(const float4*)(timg + (size_t)yu * IMG_W + x0);
    float4 tm = *(const float4*)(trow + x0);
    float hu = 0.f, hm = 0.f;
    if (is_edge) {
        hu = timg[(size_t)yu * IMG_W + hcol];
        hm = trow[hcol];
    }

    float sum = 0.0f;

    #pragma unroll 4
    for (int y = ys; y < ye; y++) {
        const int dd = (y < IMG_H - 1) ? IMG_W : 0;    // clamped next row
        const float4 td = *(const float4*)(trow + dd + x0);
        const float4 pp = *(const float4*)(prow + x0);
        float hd = 0.f;
        if (is_edge) hd = trow[dd + hcol];

        // vertical running sums (exact: values are 0.0 / 1.0)
        float4 vs;
        vs.x = tu.x + tm.x + td.x;
        vs.y = tu.y + tm.y + td.y;
        vs.z = tu.z + tm.z + td.z;
        vs.w = tu.w + tm.w + td.w;
        const float hvs = hu + hm + hd;

        // neighbor column sums across lanes
        float ls = __shfl_up_sync  (0xFFFFFFFFu, vs.w, 1);
        float rs = __shfl_down_sync(0xFFFFFFFFu, vs.x, 1);
        if (lane == 0)  ls = hvs;
        if (lane == 31) rs = hvs;

        // horizontal 3-tap sums; boundary <=> window sum in [1,8] <=> |s-4.5|<4
        const float s0 = ls   + vs.x + vs.y;
        const float s1 = vs.x + vs.y + vs.z;
        const float s2 = vs.y + vs.z + vs.w;
        const float s3 = vs.z + vs.w + rs;

        float arg, w;
        arg = (tm.x > 0.5f) ? pp.x : (1.0f - pp.x);
        w   = (fabsf(s0 - 4.5f) < 4.0f) ? 3.0f : 1.0f;
        sum = fmaf(w, -__logf(arg), sum);

        arg = (tm.y > 0.5f) ? pp.y : (1.0f - pp.y);
        w   = (fabsf(s1 - 4.5f) < 4.0f) ? 3.0f : 1.0f;
        sum = fmaf(w, -__logf(arg), sum);

        arg = (tm.z > 0.5f) ? pp.z : (1.0f - pp.z);
        w   = (fabsf(s2 - 4.5f) < 4.0f) ? 3.0f : 1.0f;
        sum = fmaf(w, -__logf(arg), sum);

        arg = (tm.w > 0.5f) ? pp.w : (1.0f - pp.w);
        w   = (fabsf(s3 - 4.5f) < 4.0f) ? 3.0f : 1.0f;
        sum = fmaf(w, -__logf(arg), sum);

        tu = tm;  tm = td;
        hu = hm;  hm = hd;
        trow += IMG_W;  prow += IMG_W;
    }

    // ---- one block reduction at exit (fp32) ----
    #pragma unroll
    for (int off = 16; off > 0; off >>= 1)
        sum += __shfl_xor_sync(0xFFFFFFFFu, sum, off);
    if (lane == 0) s_warp[wid] = sum;
    __syncthreads();

    if (tid == 0) {
        float v = 0.0f;
        #pragma unroll
        for (int i = 0; i < 8; i++) v += s_warp[i];
        g_partial[blockIdx.x] = v;
        __threadfence();
        const unsigned done = atomicAdd(&g_count, 1u);
        s_last = (done == GRID - 1);
    }
    __syncthreads();

    // ---- last block: final fp32 tree reduction over 864 partials ----
    if (s_last) {
        __threadfence();
        float v = g_partial[tid] + g_partial[tid + 256] + g_partial[tid + 512];
        if (tid < GRID - 768) v += g_partial[tid + 768];
        #pragma unroll
        for (int off = 16; off > 0; off >>= 1)
            v += __shfl_xor_sync(0xFFFFFFFFu, v, off);
        if (lane == 0) s_warp[wid] = v;
        __syncthreads();
        if (tid == 0) {
            float t = 0.0f;
            #pragma unroll
            for (int i = 0; i < 8; i++) t += s_warp[i];
            out[0] = (float)((double)t / NPIXD);
            g_count = 0;   // restore for next graph replay (deterministic)
        }
    }
}

extern "C" void kernel_launch(void* const* d_in, const int* in_sizes, int n_in,
                              void* d_out, int out_size)
{
    const float* pred   = (const float*)d_in[0];
    const float* target = (const float*)d_in[1];
    float* out = (float*)d_out;

    babce_kernel<<<GRID, 256>>>(pred, target, out);
}